// round 3
// baseline (speedup 1.0000x reference)
#include <cuda_runtime.h>

#define NN 512          // T = U = 512
#define BDIM 512
#define C_CONST 1.0f
#define GEPS 1e-9f
#define MAXB 64

__device__ float g_costs[MAXB];

// trans(x_val, y_prev, z_other) with a = x_val - y_prev, b = x_val - z_other,
// gamma = 1:  c + (1-g) * softmin2(a^2, b^2)
__device__ __forceinline__ float transf(float a, float b) {
    float u = a * b;
    // (1 - g) = 0.5 * (1 + u / sqrt(u^2 + eps))
    float w = 0.5f * (1.0f + u * rsqrtf(fmaf(u, u, GEPS)));
    float A = a * a;
    float B = b * b;
    float m = fminf(A, B);
    float M = fmaxf(A, B);
    // softmin2 = m - log(1 + exp(m - M))
    float sm = m - __logf(1.0f + __expf(m - M));
    return fmaf(w, sm, C_CONST);
}

__global__ __launch_bounds__(BDIM, 1)
void soft_msm_kernel(const float* __restrict__ x, const float* __restrict__ y) {
    __shared__ float sx[NN];     // x values for this batch
    __shared__ float sau[NN];    // x[i] - x[i-1]
    __shared__ float buf[3][NN]; // rotating anti-diagonal buffers

    const int b   = blockIdx.x;
    const int tid = threadIdx.x;
    const float* xb = x + b * NN;
    const float* yb = y + b * NN;

    // per-thread column constants
    const float yj   = yb[tid];
    const float yjm1 = (tid > 0) ? yb[tid - 1] : 0.0f;
    const float al   = yj - yjm1;              // a for the 'left' transition

    sx[tid] = xb[tid];
    __syncthreads();
    sau[tid] = (tid > 0) ? (sx[tid] - sx[tid - 1]) : 0.0f;
    const float x0 = sx[0];

    // d = 0 : C[0,0] = (x0 - y0)^2   (thread 0 only; its yj == y0)
    float curC = 0.0f;       // this thread's C on its most recent diagonal (== C[i-1,j] next step)
    float pjm1_prev = 0.0f;  // neighbor's value one diagonal back (becomes prev2[j-1] next step)
    if (tid == 0) {
        float d0 = x0 - yj;
        curC = d0 * d0;
        buf[0][0] = curC;
    }
    __syncthreads();

    // rotating buffer pointers: at d, cur = d%3, prev = (d-1)%3, prev2 = (d-2)%3
    float* curb   = buf[1];
    float* prevb  = buf[0];
    float* prev2b = buf[2];

    for (int d = 1; d < 2 * NN - 1; ++d) {
        const int i = d - tid;           // row index for this thread on diagonal d
        if (i >= 0 && i < NN) {
            if (i == 0) {
                // row-0 boundary: C[0,j] = C[0,j-1] + trans(y_j, y_{j-1}, x_0)
                float pjm1 = prevb[tid - 1];
                float bx = x0 - yj;
                curC = pjm1 + transf(al, -bx);
                pjm1_prev = pjm1;
            } else if (tid == 0) {
                // col-0 boundary: C[i,0] = C[i-1,0] + trans(x_i, x_{i-1}, y_0)
                float xi = sx[i];
                float bx = xi - yj;      // yj == y0 for tid 0
                curC = curC + transf(sau[i], bx);
            } else {
                float xi = sx[i];
                float bx = xi - yj;      // x_i - y_j
                float match = bx * bx;
                float up   = transf(sau[i], bx);   // trans(x_i, x_{i-1}, y_j)
                float left = transf(al,  -bx);     // trans(y_j, y_{j-1}, x_i)

                float pjm1 = prevb[tid - 1];       // C[i, j-1]
                float dd = pjm1_prev + match;      // C[i-1,j-1] + match
                float du = curC      + up;         // C[i-1,j]   + up (own register)
                float cl = pjm1      + left;       // C[i, j-1]  + left

                float m = fminf(dd, fminf(du, cl));
                float s = __expf(m - dd) + __expf(m - du) + __expf(m - cl);
                curC = m - __logf(s);
                pjm1_prev = pjm1;
            }
            curb[tid] = curC;
        }
        // rotate: next cur is old prev2, next prev is old cur, next prev2 is old prev
        float* t = prev2b; prev2b = prevb; prevb = curb; curb = t;
        __syncthreads();
    }

    if (tid == NN - 1) g_costs[b] = curC;   // C[511,511]
}

__global__ void reduce_kernel(float* __restrict__ out, int B) {
    __shared__ float s[MAXB];
    int t = threadIdx.x;
    s[t] = (t < B) ? g_costs[t] : 0.0f;
    __syncthreads();
    for (int off = MAXB / 2; off > 0; off >>= 1) {
        if (t < off) s[t] += s[t + off];
        __syncthreads();
    }
    if (t == 0) out[0] = s[0] * (1.0f / (float)B);
}

extern "C" void kernel_launch(void* const* d_in, const int* in_sizes, int n_in,
                              void* d_out, int out_size) {
    const float* x = (const float*)d_in[0];
    const float* y = (const float*)d_in[1];
    int B = in_sizes[0] / NN;   // 64 * 1 * 512 / 512 = 64
    if (B > MAXB) B = MAXB;
    soft_msm_kernel<<<B, BDIM>>>(x, y);
    reduce_kernel<<<1, MAXB>>>((float*)d_out, B);
}